// round 13
// baseline (speedup 1.0000x reference)
#include <cuda_runtime.h>
#include <cstdint>

// EA-LSTM fused persistent kernel, round 12: round-11 cluster-4 multicast
// pipeline with the PRODUCER FULLY DECOUPLED from consumer step barriers:
//  - step barriers are named bar.sync(1, 768) over consumers only
//  - producer computes out[t-1] from a double-buffered h_t (no barrier
//    participation; safety via the tile-issue ordering)
// B=1024, T=365, Dd=32, Ds=27, H=256, 3H=768, O=1.
//
// 128 CTAs x 800 threads, cluster (4,1,1). CTA owns M=8 batch elems.
// Warps 0-23 consume (group g = warp/8 takes rows [8g,8g+8) of each 24-row
// tile); warp 24 produces tiles (gatekeeper collects per-stage named-barrier
// arrivals, issues cluster empty-arrives + bulk multicast of its 1/4 slice)
// and computes the previous step's output dot.
// Owners: g0 -> {m0,m1}, g1 -> {m2,m3}, g2 -> {m4..m7}; groups publish only
// non-owned partials. Bit-exact fp32 accumulation via packed f32x2.

#define B_      1024
#define T_      365
#define DD      32
#define DS      27
#define H_      256
#define G3      768
#define M_      8
#define KTOT    288
#define KT      24
#define NTILES  12
#define THREADS 800
#define NCONS   768
#define CTAS    (B_ / M_)          // 128
#define CLUSTER 4
#define PSTRIDE 256
#define HT_S    264

#define TILE_BYTES  73728
#define WG_OFF      49152
#define SLICE_BYTES (TILE_BYTES / CLUSTER)   // 18432
#define TOTAL_TILES (T_ * NTILES)            // 4380

#define XH_FLOATS   (KTOT * M_)              // 2304
#define PUB_SLOTS   24
#define DSM_BYTES   (2 * TILE_BYTES + PUB_SLOTS * PSTRIDE * 8 + XH_FLOATS * 4)

typedef unsigned long long u64;

__device__ __align__(128) unsigned char WT[NTILES * TILE_BYTES];

// ---------- packed fp32x2 helpers ----------
__device__ __forceinline__ u64 pack2(float lo, float hi) {
    u64 r; asm("mov.b64 %0, {%1, %2};" : "=l"(r) : "f"(lo), "f"(hi)); return r;
}
__device__ __forceinline__ void unpack2(u64 v, float& lo, float& hi) {
    asm("mov.b64 {%0, %1}, %2;" : "=f"(lo), "=f"(hi) : "l"(v));
}
__device__ __forceinline__ void fma2(u64& d, u64 a, u64 b) {
    asm("fma.rn.f32x2 %0, %1, %2, %0;" : "+l"(d) : "l"(a), "l"(b));
}
__device__ __forceinline__ void add2(u64& d, u64 a) {
    asm("add.rn.f32x2 %0, %0, %1;" : "+l"(d) : "l"(a));
}
__device__ __forceinline__ float sigmoidf_(float x) {
    return __fdividef(1.0f, 1.0f + __expf(-x));
}
__device__ __forceinline__ float tanhf_(float x) {
    float e = __expf(-2.0f * x);
    return __fdividef(1.0f - e, 1.0f + e);
}

// ---------- mbarrier / cluster helpers ----------
#define MBARRIER_INIT(addr, count) \
    asm volatile("mbarrier.init.shared.b64 [%0], %1;" \
                 :: "r"((uint32_t)(addr)), "r"((uint32_t)(count)) : "memory")

#define MBARRIER_EXPECT_TX(addr, bytes) \
    asm volatile("mbarrier.arrive.expect_tx.shared.b64 _, [%0], %1;" \
                 :: "r"((uint32_t)(addr)), "r"((uint32_t)(bytes)) : "memory")

#define MBARRIER_WAIT_PARITY(addr, parity) do {                               \
    uint32_t _m = (uint32_t)(addr), _p = (uint32_t)(parity), _d;              \
    asm volatile("{\n\t.reg .pred p;\n\t"                                     \
        "mbarrier.try_wait.parity.acquire.cta.shared::cta.b64 p, [%1], %2;\n\t" \
        "selp.b32 %0, 1, 0, p;\n\t}"                                          \
        : "=r"(_d) : "r"(_m), "r"(_p) : "memory");                            \
    if (!_d) {                                                                \
        asm volatile("{\n\t.reg .pred P1;\n\t"                                \
            "WL_%=:\n\t"                                                      \
            "mbarrier.try_wait.parity.acquire.cta.shared::cta.b64 P1, [%0], %1, 0x989680;\n\t" \
            "@P1 bra.uni WD_%=;\n\t"                                          \
            "bra.uni WL_%=;\n\t"                                              \
            "WD_%=:\n\t}"                                                     \
            :: "r"(_m), "r"(_p) : "memory");                                  \
    }                                                                         \
} while (0)

#define MBARRIER_ARRIVE_CLUSTER(addr, rnk) \
    asm volatile("{\n\t.reg .b32 ra;\n\t"                       \
        "mapa.shared::cluster.u32 ra, %0, %1;\n\t"              \
        "mbarrier.arrive.release.cluster.shared::cluster.b64 _, [ra];\n\t}" \
        :: "r"((uint32_t)(addr)), "r"((uint32_t)(rnk)) : "memory")

#define CLUSTER_SYNC() do {                                             \
    asm volatile("barrier.cluster.arrive.aligned;" ::: "memory");       \
    asm volatile("barrier.cluster.wait.aligned;" ::: "memory");         \
} while (0)

#define CONS_BAR() asm volatile("bar.sync 1, %0;" :: "n"(NCONS) : "memory")
#define STAGE_ARRIVE(s) \
    asm volatile("bar.arrive %0, %1;" :: "r"(2 + (s)), "n"(THREADS) : "memory")
#define STAGE_COLLECT(s) \
    asm volatile("bar.sync %0, %1;" :: "r"(2 + (s)), "n"(THREADS) : "memory")

__device__ __forceinline__ uint32_t smem_u32(const void* p) {
    return (uint32_t)__cvta_generic_to_shared(p);
}
__device__ __forceinline__ void bulk_mc(uint32_t dst, const void* src,
                                        uint32_t bytes, uint32_t mbar) {
    asm volatile(
        "cp.async.bulk.shared::cluster.global.mbarrier::complete_tx::bytes"
        ".multicast::cluster [%0], [%1], %2, [%3], %4;"
        :: "r"(dst), "l"((u64)(uintptr_t)src), "r"(bytes), "r"(mbar),
           "h"((uint16_t)((1u << CLUSTER) - 1u))
        : "memory");
}

// ---------- weight repack (tile-major) ----------
__global__ void __launch_bounds__(256)
repack_kernel(const float* __restrict__ Wih, const float* __restrict__ Whh) {
    const int k   = blockIdx.x;        // unified k: 0..287
    const int col = threadIdx.x;       // 0..255
    const int tile = k / KT, kl = k % KT;
    const float* s = (k < DD) ? (Wih + k * G3) : (Whh + (k - DD) * G3);
    unsigned char* base = WT + (size_t)tile * TILE_BYTES;
    *(float2*)(base + kl * 2048 + col * 8) = make_float2(s[col], s[256 + col]);
    *(float*)(base + WG_OFF + kl * 1024 + col * 4) = s[512 + col];
}

// ---------- main kernel ----------
__global__ void __launch_bounds__(THREADS, 1)
ealstm_kernel(const float* __restrict__ xd,      // [B, T, DD]
              const float* __restrict__ xs,      // [B, DS]
              const float* __restrict__ Wsh,     // [DS, H]
              const float* __restrict__ bias,    // [3H]
              const float* __restrict__ bias_s,  // [H]
              const float* __restrict__ Wout,    // [H, 1]
              const float* __restrict__ bout,    // [1]
              float* __restrict__ out)           // [B, T, 1]
{
    __shared__ float h_t[2][M_][HT_S];              // double-buffered transposed h
    __shared__ __align__(8) u64 mbar[4];            // full0, full1, empty0, empty1
    extern __shared__ __align__(128) unsigned char dsm[];
    unsigned char* stg = dsm;                                  // 2 x TILE_BYTES
    u64*   pub = (u64*)(dsm + 2 * TILE_BYTES);                 // [24][PSTRIDE]
    float* xh  = (float*)(dsm + 2 * TILE_BYTES + PUB_SLOTS * PSTRIDE * 8);

    const int tid  = threadIdx.x;
    const int warp = tid >> 5;
    const int lane = tid & 31;
    const int b0   = blockIdx.x * M_;

    uint32_t rank;
    asm("mov.u32 %0, %%cluster_ctarank;" : "=r"(rank));

    const uint32_t mb = smem_u32(mbar);
    const uint32_t full_b[2]  = { mb,      mb + 8  };
    const uint32_t empty_b[2] = { mb + 16, mb + 24 };

    if (tid == 0) {
        MBARRIER_INIT(full_b[0], 1);
        MBARRIER_INIT(full_b[1], 1);
        MBARRIER_INIT(empty_b[0], CLUSTER);
        MBARRIER_INIT(empty_b[1], CLUSTER);
    }

    // zero h region of xh
    for (int i = DD * M_ + tid; i < KTOT * M_; i += THREADS) xh[i] = 0.0f;

    // stage x_t for t = 0 (warps 8..15)
    if (warp >= 8 && warp < 16) {
        const int col0 = tid & 255;
        const int m = col0 >> 5, k = col0 & 31;
        xh[k * M_ + m] = xd[((size_t)(b0 + m) * T_ + 0) * DD + k];
    }

    __syncthreads();     // mbarrier init + xh + x(0) visible CTA-wide
    CLUSTER_SYNC();      // barriers visible cluster-wide before any multicast

    if (warp == 24) {
        // ========= producer / gatekeeper / delayed out-dot warp =========
        float wout[8];
        #pragma unroll
        for (int q = 0; q < 8; q++) wout[q] = Wout[lane + 32 * q];
        const float b_out0 = bout[0];
        const uint32_t stg0 = smem_u32(stg) + rank * SLICE_BYTES;

        // prologue: queue tiles 0 and 1 (fresh empty barriers pass at parity 1)
        if (lane == 0) {
            #pragma unroll
            for (int q = 0; q < 2; q++) {
                const int s = q & 1;
                MBARRIER_WAIT_PARITY(empty_b[s], 1);
                MBARRIER_EXPECT_TX(full_b[s], TILE_BYTES);
                bulk_mc(stg0 + s * TILE_BYTES,
                        WT + (size_t)q * TILE_BYTES + rank * SLICE_BYTES,
                        SLICE_BYTES, full_b[s]);
            }
        }

        for (int t = 0; t < T_; t++) {
            // issue tiles 12t+2 .. 12t+13 (collect frees their stages first)
            for (int i = 0; i < NTILES; i++) {
                const int m = 12 * t + i + 2;
                if (m < TOTAL_TILES) {
                    const int s = m & 1;
                    STAGE_COLLECT(s);              // consumers done with tile m-2
                    if (lane < CLUSTER)
                        MBARRIER_ARRIVE_CLUSTER(empty_b[s], lane);
                    if (lane == 0) {
                        MBARRIER_WAIT_PARITY(empty_b[s], ((m >> 1) & 1) ^ 1);
                        MBARRIER_EXPECT_TX(full_b[s], TILE_BYTES);
                        bulk_mc(stg0 + s * TILE_BYTES,
                                WT + (size_t)(m % NTILES) * TILE_BYTES + rank * SLICE_BYTES,
                                SLICE_BYTES, full_b[s]);
                    }
                }
            }

            // delayed output dot for step t-1. Safe: buffer (t-1)&1 is next
            // rewritten at update(t+1), which requires step-t+1 tiles that we
            // have not issued yet.
            if (t > 0) {
                const float (*hp)[HT_S] = h_t[(t - 1) & 1];
                #pragma unroll
                for (int m = 0; m < M_; m++) {
                    float a = 0.0f;
                    #pragma unroll
                    for (int q = 0; q < 8; q++)
                        a = fmaf(hp[m][lane + 32 * q], wout[q], a);
                    #pragma unroll
                    for (int off = 16; off > 0; off >>= 1)
                        a += __shfl_down_sync(0xffffffffu, a, off);
                    if (lane == 0)
                        out[(size_t)(b0 + m) * T_ + (t - 1)] = a + b_out0;
                }
            }
        }

        __syncthreads();   // consumers finished step T-1 update
        {
            const float (*hp)[HT_S] = h_t[(T_ - 1) & 1];
            #pragma unroll
            for (int m = 0; m < M_; m++) {
                float a = 0.0f;
                #pragma unroll
                for (int q = 0; q < 8; q++)
                    a = fmaf(hp[m][lane + 32 * q], wout[q], a);
                #pragma unroll
                for (int off = 16; off > 0; off >>= 1)
                    a += __shfl_down_sync(0xffffffffu, a, off);
                if (lane == 0)
                    out[(size_t)(b0 + m) * T_ + (T_ - 1)] = a + b_out0;
            }
        }
    } else {
        // =================== consumer warps (0..23) ===================
        const int grp = warp >> 3;             // 0,1,2
        const int col = tid & 255;
        const int kt0 = 8 * grp;               // my 8 rows within each tile
        const int mb_own = (grp == 2) ? 4 : 2 * grp;
        const int nm     = (grp == 2) ? 4 : 2;

        float bf = 0.0f, bo = 0.0f, bg = 0.0f;
        if (grp == 0) { bf = bias[col]; bo = bias[H_ + col]; bg = bias[2 * H_ + col]; }

        // cell state + entity-aware input gate for OWNED m's
        float c[4], ig[4];
        {
            float s[4];
            const float bs = bias_s[col];
            #pragma unroll
            for (int i = 0; i < 4; i++) { s[i] = bs; c[i] = 0.0f; }
            #pragma unroll 1
            for (int k = 0; k < DS; k++) {
                const float w = Wsh[k * H_ + col];
                for (int i = 0; i < nm; i++)
                    s[i] = fmaf(xs[(b0 + mb_own + i) * DS + k], w, s[i]);
            }
            #pragma unroll
            for (int i = 0; i < 4; i++) ig[i] = sigmoidf_(s[i]);
        }

        int n = 0;
        for (int t = 0; t < T_; t++) {
            u64 aF[4], aO[4], aG[4];
            {
                const u64 bf2 = pack2(bf, bf), bo2 = pack2(bo, bo), bg2 = pack2(bg, bg);
                #pragma unroll
                for (int p = 0; p < 4; p++) { aF[p] = bf2; aO[p] = bo2; aG[p] = bg2; }
            }

            #pragma unroll 1
            for (int i = 0; i < NTILES; i++, n++) {
                const int s = n & 1;
                MBARRIER_WAIT_PARITY(full_b[s], (n >> 1) & 1);

                const unsigned char* base = stg + s * TILE_BYTES;
                const float* hb = xh + (24 * i + kt0) * M_;
                #pragma unroll
                for (int kl = 0; kl < 8; kl++) {
                    const int kt = kt0 + kl;
                    const float2 wfo = *(const float2*)(base + kt * 2048 + col * 8);
                    const float  wg  = *(const float*)(base + WG_OFF + kt * 1024 + col * 4);
                    const u64 wf2 = pack2(wfo.x, wfo.x);
                    const u64 wo2 = pack2(wfo.y, wfo.y);
                    const u64 wg2 = pack2(wg, wg);
                    const ulonglong2 hA = *(const ulonglong2*)(hb + kl * M_);
                    const ulonglong2 hB = *(const ulonglong2*)(hb + kl * M_ + 4);
                    fma2(aF[0], wf2, hA.x); fma2(aF[1], wf2, hA.y);
                    fma2(aF[2], wf2, hB.x); fma2(aF[3], wf2, hB.y);
                    fma2(aO[0], wo2, hA.x); fma2(aO[1], wo2, hA.y);
                    fma2(aO[2], wo2, hB.x); fma2(aO[3], wo2, hB.y);
                    fma2(aG[0], wg2, hA.x); fma2(aG[1], wg2, hA.y);
                    fma2(aG[2], wg2, hB.x); fma2(aG[3], wg2, hB.y);
                }
                STAGE_ARRIVE(s);   // non-blocking; gatekeeper collects
            }

            // publish non-owned partials (compact slots; gate-major F,O,G)
            if (grp == 0) {           // publishes p1,p2,p3  (slots 0..8)
                pub[(0) * PSTRIDE + col] = aF[1];
                pub[(1) * PSTRIDE + col] = aF[2];
                pub[(2) * PSTRIDE + col] = aF[3];
                pub[(3) * PSTRIDE + col] = aO[1];
                pub[(4) * PSTRIDE + col] = aO[2];
                pub[(5) * PSTRIDE + col] = aO[3];
                pub[(6) * PSTRIDE + col] = aG[1];
                pub[(7) * PSTRIDE + col] = aG[2];
                pub[(8) * PSTRIDE + col] = aG[3];
            } else if (grp == 1) {    // publishes p0,p2,p3  (slots 9..17)
                pub[(9)  * PSTRIDE + col] = aF[0];
                pub[(10) * PSTRIDE + col] = aF[2];
                pub[(11) * PSTRIDE + col] = aF[3];
                pub[(12) * PSTRIDE + col] = aO[0];
                pub[(13) * PSTRIDE + col] = aO[2];
                pub[(14) * PSTRIDE + col] = aO[3];
                pub[(15) * PSTRIDE + col] = aG[0];
                pub[(16) * PSTRIDE + col] = aG[2];
                pub[(17) * PSTRIDE + col] = aG[3];
            } else {                  // publishes p0,p1     (slots 18..23)
                pub[(18) * PSTRIDE + col] = aF[0];
                pub[(19) * PSTRIDE + col] = aF[1];
                pub[(20) * PSTRIDE + col] = aO[0];
                pub[(21) * PSTRIDE + col] = aO[1];
                pub[(22) * PSTRIDE + col] = aG[0];
                pub[(23) * PSTRIDE + col] = aG[1];
            }

            CONS_BAR();   // BAR1 (consumers only): partials exchanged

            float (*ht)[HT_S] = h_t[t & 1];

            // ---- owner update ----
            if (grp == 0) {            // pair 0 -> m0,m1
                u64 tF = aF[0], tO = aO[0], tG = aG[0];
                add2(tF, pub[(9)  * PSTRIDE + col]); add2(tF, pub[(18) * PSTRIDE + col]);
                add2(tO, pub[(12) * PSTRIDE + col]); add2(tO, pub[(20) * PSTRIDE + col]);
                add2(tG, pub[(15) * PSTRIDE + col]); add2(tG, pub[(22) * PSTRIDE + col]);
                float f0, f1, o0, o1, g0, g1;
                unpack2(tF, f0, f1); unpack2(tO, o0, o1); unpack2(tG, g0, g1);
                c[0] = sigmoidf_(f0) * c[0] + ig[0] * tanhf_(g0);
                c[1] = sigmoidf_(f1) * c[1] + ig[1] * tanhf_(g1);
                const float h0 = sigmoidf_(o0) * tanhf_(c[0]);
                const float h1 = sigmoidf_(o1) * tanhf_(c[1]);
                *(u64*)(xh + (DD + col) * M_) = pack2(h0, h1);
                ht[0][col] = h0; ht[1][col] = h1;
            } else if (grp == 1) {     // pair 1 -> m2,m3 (+ stage x(t+1))
                u64 tF = aF[1], tO = aO[1], tG = aG[1];
                add2(tF, pub[(0) * PSTRIDE + col]); add2(tF, pub[(19) * PSTRIDE + col]);
                add2(tO, pub[(3) * PSTRIDE + col]); add2(tO, pub[(21) * PSTRIDE + col]);
                add2(tG, pub[(6) * PSTRIDE + col]); add2(tG, pub[(23) * PSTRIDE + col]);
                float f0, f1, o0, o1, g0, g1;
                unpack2(tF, f0, f1); unpack2(tO, o0, o1); unpack2(tG, g0, g1);
                c[0] = sigmoidf_(f0) * c[0] + ig[0] * tanhf_(g0);
                c[1] = sigmoidf_(f1) * c[1] + ig[1] * tanhf_(g1);
                const float h2 = sigmoidf_(o0) * tanhf_(c[0]);
                const float h3 = sigmoidf_(o1) * tanhf_(c[1]);
                *(u64*)(xh + (DD + col) * M_ + 2) = pack2(h2, h3);
                ht[2][col] = h2; ht[3][col] = h3;
                if (t + 1 < T_) {
                    const int m = col >> 5, k = col & 31;
                    xh[k * M_ + m] = xd[((size_t)(b0 + m) * T_ + (t + 1)) * DD + k];
                }
            } else {                   // pairs 2,3 -> m4..m7
                float hn[4];
                #pragma unroll
                for (int i = 0; i < 2; i++) {
                    const int p = 2 + i;
                    u64 tF = aF[p], tO = aO[p], tG = aG[p];
                    add2(tF, pub[(1 + i)  * PSTRIDE + col]); add2(tF, pub[(10 + i) * PSTRIDE + col]);
                    add2(tO, pub[(4 + i)  * PSTRIDE + col]); add2(tO, pub[(13 + i) * PSTRIDE + col]);
                    add2(tG, pub[(7 + i)  * PSTRIDE + col]); add2(tG, pub[(16 + i) * PSTRIDE + col]);
                    float f0, f1, o0, o1, g0, g1;
                    unpack2(tF, f0, f1); unpack2(tO, o0, o1); unpack2(tG, g0, g1);
                    const int i0 = 2 * i, i1 = 2 * i + 1;
                    c[i0] = sigmoidf_(f0) * c[i0] + ig[i0] * tanhf_(g0);
                    c[i1] = sigmoidf_(f1) * c[i1] + ig[i1] * tanhf_(g1);
                    hn[i0] = sigmoidf_(o0) * tanhf_(c[i0]);
                    hn[i1] = sigmoidf_(o1) * tanhf_(c[i1]);
                }
                *(float4*)(xh + (DD + col) * M_ + 4) =
                    make_float4(hn[0], hn[1], hn[2], hn[3]);
                ht[4][col] = hn[0]; ht[5][col] = hn[1];
                ht[6][col] = hn[2]; ht[7][col] = hn[3];
            }

            CONS_BAR();   // BAR2 (consumers only): h(t), h_t(t), x(t+1) ready
        }

        __syncthreads();   // rejoin producer for its final out-dot
    }

    CLUSTER_SYNC();    // no CTA exits while peer multicasts could be in flight
}

extern "C" void kernel_launch(void* const* d_in, const int* in_sizes, int n_in,
                              void* d_out, int out_size) {
    const float* xd     = (const float*)d_in[0];  // x_dynamic [1024,365,32]
    const float* xs     = (const float*)d_in[1];  // x_static  [1024,27]
    const float* Wih    = (const float*)d_in[2];  // [32,768]
    const float* Whh    = (const float*)d_in[3];  // [256,768]
    const float* Wsh    = (const float*)d_in[4];  // [27,256]
    const float* bias   = (const float*)d_in[5];  // [768]
    const float* bias_s = (const float*)d_in[6];  // [256]
    const float* Wout   = (const float*)d_in[7];  // [256,1]
    const float* bout   = (const float*)d_in[8];  // [1]
    float* out = (float*)d_out;                   // [1024,365,1]

    (void)cudaFuncSetAttribute(ealstm_kernel,
                               cudaFuncAttributeMaxDynamicSharedMemorySize,
                               DSM_BYTES);
    (void)cudaGetLastError();

    repack_kernel<<<KTOT, 256>>>(Wih, Whh);

    cudaLaunchConfig_t cfg = {};
    cfg.gridDim = dim3(CTAS, 1, 1);
    cfg.blockDim = dim3(THREADS, 1, 1);
    cfg.dynamicSmemBytes = DSM_BYTES;
    cudaLaunchAttribute attrs[1];
    attrs[0].id = cudaLaunchAttributeClusterDimension;
    attrs[0].val.clusterDim.x = CLUSTER;
    attrs[0].val.clusterDim.y = 1;
    attrs[0].val.clusterDim.z = 1;
    cfg.attrs = attrs;
    cfg.numAttrs = 1;
    (void)cudaLaunchKernelEx(&cfg, ealstm_kernel,
                             xd, xs, Wsh, bias, bias_s, Wout, bout, out);
}

// round 14
// speedup vs baseline: 1.4153x; 1.4153x over previous
#include <cuda_runtime.h>

// EA-LSTM fused persistent kernel, round 13: EXACT round-4 structure (best,
// 4620us) with ONE change — slim packed weights (float2 wf,wo + float wg)
// on a unified k axis, replacing the float4-with-wasted-lane layout.
// Clean A/B vs R4 (isolates weight layout) and vs R7 (isolates update style).
// B=1024, T=365, Dd=32, Ds=27, H=256, 3H=768, O=1.
// Grid: 128 CTAs x 512 threads, M=8 batch elems per CTA. Thread (grp,col):
//   grp 0: bias + unified k in [0,144)   (x rows 0..31 + h rows 0..111)
//   grp 1:        unified k in [144,288) (h rows 112..255) -> partials SMEM
// grp 0 combines + state update; grp 1 stages x(t+1) and does the out-dot.
// All accumulation bit-exact fp32 (Blackwell packed f32x2).

#define B_      1024
#define T_      365
#define DD      32
#define DS      27
#define H_      256
#define G3      768
#define M_      8
#define KTOT    288            // 32 x-k + 256 h-k (unified)
#define KG      144            // k per group
#define THREADS 512
#define CTAS    (B_ / M_)      // 128
#define PS_STRIDE 13           // padded partial stride (u64 per column)
#define HT_S    264

typedef unsigned long long u64;

// slim packed weights, unified k axis (k<32 -> W_ih row k, else W_hh row k-32)
__device__ float2 WfoP[KTOT][256];   // (wf, wo) per column
__device__ float  WgP [KTOT][256];   // wg per column

__device__ __forceinline__ u64 pack2(float lo, float hi) {
    u64 r; asm("mov.b64 %0, {%1, %2};" : "=l"(r) : "f"(lo), "f"(hi)); return r;
}
__device__ __forceinline__ void unpack2(u64 v, float& lo, float& hi) {
    asm("mov.b64 {%0, %1}, %2;" : "=f"(lo), "=f"(hi) : "l"(v));
}
__device__ __forceinline__ void fma2(u64& d, u64 a, u64 b) {
    asm("fma.rn.f32x2 %0, %1, %2, %0;" : "+l"(d) : "l"(a), "l"(b));
}
__device__ __forceinline__ void add2(u64& d, u64 a) {
    asm("add.rn.f32x2 %0, %0, %1;" : "+l"(d) : "l"(a));
}
__device__ __forceinline__ float sigmoidf_(float x) {
    return __fdividef(1.0f, 1.0f + __expf(-x));
}
__device__ __forceinline__ float tanhf_(float x) {
    float e = __expf(-2.0f * x);
    return __fdividef(1.0f - e, 1.0f + e);
}

__global__ void __launch_bounds__(256)
repack_kernel(const float* __restrict__ Wih, const float* __restrict__ Whh) {
    const int k   = blockIdx.x;        // unified k: 0..287
    const int col = threadIdx.x;       // 0..255
    const float* s = (k < DD) ? (Wih + k * G3) : (Whh + (k - DD) * G3);
    WfoP[k][col] = make_float2(s[col], s[256 + col]);
    WgP [k][col] = s[512 + col];
}

__global__ void __launch_bounds__(THREADS, 1)
ealstm_kernel(const float* __restrict__ xd,      // [B, T, DD]
              const float* __restrict__ xs,      // [B, DS]
              const float* __restrict__ Wsh,     // [DS, H]
              const float* __restrict__ bias,    // [3H]
              const float* __restrict__ bias_s,  // [H]
              const float* __restrict__ Wout,    // [H, 1]
              const float* __restrict__ bout,    // [1]
              float* __restrict__ out)           // [B, T, 1]
{
    __shared__ __align__(16) float xh[KTOT * M_];  // k<32: x_t, else h (stride 8)
    __shared__ float h_t[M_][HT_S];                // h transposed for out-dot
    __shared__ u64   p_s[H_ * PS_STRIDE];          // group-1 partial gate sums

    const int j    = threadIdx.x;
    const int grp  = j >> 8;                // 0 or 1
    const int col  = j & 255;               // gate/h column
    const int b0   = blockIdx.x * M_;
    const int lane = j & 31;
    const int warp = j >> 5;
    const int k0   = grp * KG;              // unified k range start

    // zero h region of xh (indices [DD*M_, KTOT*M_))
    for (int idx = DD * M_ + j; idx < KTOT * M_; idx += THREADS) xh[idx] = 0.0f;

    // stage x_t for t = 0 (group 1's 256 threads)
    if (grp == 1) {
        const int m = col >> 5, k = col & 31;
        xh[k * M_ + m] = xd[((size_t)(b0 + m) * T_ + 0) * DD + k];
    }

    // per-thread gate biases (group 0 seeds accumulators)
    float bf = 0.0f, bo = 0.0f, bg = 0.0f;
    if (grp == 0) { bf = bias[col]; bo = bias[H_ + col]; bg = bias[2 * H_ + col]; }

    // entity-aware input gate (group 0 only)
    float ig[M_];
    if (grp == 0) {
        float s[M_];
        #pragma unroll
        for (int m = 0; m < M_; m++) s[m] = bias_s[col];
        #pragma unroll 1
        for (int k = 0; k < DS; k++) {
            const float w = Wsh[k * H_ + col];
            #pragma unroll
            for (int m = 0; m < M_; m++)
                s[m] = fmaf(xs[(b0 + m) * DS + k], w, s[m]);
        }
        #pragma unroll
        for (int m = 0; m < M_; m++) ig[m] = sigmoidf_(s[m]);
    }

    // per-lane output weights for the warp-level out-dot
    float wout[8];
    #pragma unroll
    for (int q = 0; q < 8; q++) wout[q] = Wout[lane + 32 * q];
    const float b_out0 = bout[0];

    float c[M_];
    #pragma unroll
    for (int m = 0; m < M_; m++) c[m] = 0.0f;

    __syncthreads();

    for (int t = 0; t < T_; t++) {
        u64 aF[4], aO[4], aG[4];
        if (grp == 0) {
            const u64 bf2 = pack2(bf, bf), bo2 = pack2(bo, bo), bg2 = pack2(bg, bg);
            #pragma unroll
            for (int p = 0; p < 4; p++) { aF[p] = bf2; aO[p] = bo2; aG[p] = bg2; }
        } else {
            #pragma unroll
            for (int p = 0; p < 4; p++) { aF[p] = 0ull; aO[p] = 0ull; aG[p] = 0ull; }
        }

        // ---- unified accumulation over this group's 144 k's ----
        {
            const float2* wfo_p = &WfoP[k0][col];
            const float*  wg_p  = &WgP[k0][col];
            const float*  hb    = xh + k0 * M_;
            #pragma unroll 4
            for (int k = 0; k < KG; k++) {
                const float2 wfo = __ldcg(wfo_p + k * 256);
                const float  wg  = __ldcg(wg_p  + k * 256);
                const u64 wf2 = pack2(wfo.x, wfo.x);
                const u64 wo2 = pack2(wfo.y, wfo.y);
                const u64 wg2 = pack2(wg, wg);
                const ulonglong2 hA = *(const ulonglong2*)(hb + k * M_);
                const ulonglong2 hB = *(const ulonglong2*)(hb + k * M_ + 4);
                fma2(aF[0], wf2, hA.x); fma2(aF[1], wf2, hA.y);
                fma2(aF[2], wf2, hB.x); fma2(aF[3], wf2, hB.y);
                fma2(aO[0], wo2, hA.x); fma2(aO[1], wo2, hA.y);
                fma2(aO[2], wo2, hB.x); fma2(aO[3], wo2, hB.y);
                fma2(aG[0], wg2, hA.x); fma2(aG[1], wg2, hA.y);
                fma2(aG[2], wg2, hB.x); fma2(aG[3], wg2, hB.y);
            }
        }

        // group 1 publishes partials (per-col contiguous layout, as R4)
        if (grp == 1) {
            u64* pp = p_s + col * PS_STRIDE;
            #pragma unroll
            for (int p = 0; p < 4; p++) {
                pp[p]     = aF[p];
                pp[4 + p] = aO[p];
                pp[8 + p] = aG[p];
            }
        }

        __syncthreads();   // partials published; xh reads of step t done

        if (grp == 0) {
            // combine partials + state update (R4's serial tail, unchanged)
            const u64* pp = p_s + col * PS_STRIDE;
            #pragma unroll
            for (int p = 0; p < 4; p++) {
                add2(aF[p], pp[p]);
                add2(aO[p], pp[4 + p]);
                add2(aG[p], pp[8 + p]);
            }
            float hn[M_];
            #pragma unroll
            for (int p = 0; p < 4; p++) {
                float f0, f1, o0, o1, g0, g1;
                unpack2(aF[p], f0, f1);
                unpack2(aO[p], o0, o1);
                unpack2(aG[p], g0, g1);
                const int m0 = 2 * p, m1 = 2 * p + 1;
                c[m0] = sigmoidf_(f0) * c[m0] + ig[m0] * tanhf_(g0);
                c[m1] = sigmoidf_(f1) * c[m1] + ig[m1] * tanhf_(g1);
                hn[m0] = sigmoidf_(o0) * tanhf_(c[m0]);
                hn[m1] = sigmoidf_(o1) * tanhf_(c[m1]);
            }
            // publish h into xh h-region (stride-8 aligned, vectorized)
            float* hd = xh + (DD + col) * M_;
            *(float4*)(hd)     = make_float4(hn[0], hn[1], hn[2], hn[3]);
            *(float4*)(hd + 4) = make_float4(hn[4], hn[5], hn[6], hn[7]);
            // transposed copy for the out-dot
            #pragma unroll
            for (int m = 0; m < M_; m++) h_t[m][col] = hn[m];
        } else {
            // stage x for t+1 (x region: disjoint from h region)
            if (t + 1 < T_) {
                const int m = col >> 5, k = col & 31;
                xh[k * M_ + m] = xd[((size_t)(b0 + m) * T_ + (t + 1)) * DD + k];
            }
        }

        __syncthreads();   // h(t), h_t(t), x(t+1) published

        // output dot: group-1 warps (8..15) own batch elems 0..7
        if (grp == 1) {
            const int w = warp - 8;   // 0..7 = batch element m
            float a = 0.0f;
            #pragma unroll
            for (int q = 0; q < 8; q++)
                a = fmaf(h_t[w][lane + 32 * q], wout[q], a);
            #pragma unroll
            for (int off = 16; off > 0; off >>= 1)
                a += __shfl_down_sync(0xffffffffu, a, off);
            if (lane == 0)
                out[(size_t)(b0 + w) * T_ + t] = a + b_out0;
        }
        // h_t isn't rewritten until after the next step's first sync, so this
        // post-sync read overlap is race-free.
    }
}

extern "C" void kernel_launch(void* const* d_in, const int* in_sizes, int n_in,
                              void* d_out, int out_size) {
    const float* xd     = (const float*)d_in[0];  // x_dynamic [1024,365,32]
    const float* xs     = (const float*)d_in[1];  // x_static  [1024,27]
    const float* Wih    = (const float*)d_in[2];  // [32,768]
    const float* Whh    = (const float*)d_in[3];  // [256,768]
    const float* Wsh    = (const float*)d_in[4];  // [27,256]
    const float* bias   = (const float*)d_in[5];  // [768]
    const float* bias_s = (const float*)d_in[6];  // [256]
    const float* Wout   = (const float*)d_in[7];  // [256,1]
    const float* bout   = (const float*)d_in[8];  // [1]
    float* out = (float*)d_out;                   // [1024,365,1]

    repack_kernel<<<KTOT, 256>>>(Wih, Whh);
    ealstm_kernel<<<CTAS, THREADS>>>(xd, xs, Wsh, bias, bias_s,
                                     Wout, bout, out);
}

// round 15
// speedup vs baseline: 1.4424x; 1.0192x over previous
#include <cuda_runtime.h>
#include <cuda_fp16.h>

// EA-LSTM fused persistent kernel, round 14: best structure (R4/R13 split-k,
// 512 thr) + FP16 WEIGHTS in a single 8-byte stream per (k,col):
//   WP[k][col] = {half wf, half wo, half wg, pad} -> ONE LDG.64 per warp-k
// (was one LDG.128 of float4). Halves both the L1 wavefront count on the
// binding L1tex pipe and the L2 weight stream (52.6 GB -> 26.3 GB).
// Accumulation stays bit-pure fp32 (packed f32x2); only weights are rounded
// to fp16 (per-weight rel err <= 4.9e-4, gate-sum rel err ~3e-4 << 1e-3).
// B=1024, T=365, Dd=32, Ds=27, H=256, 3H=768, O=1.
// Grid: 128 CTAs x 512 threads, M=8 batch elems per CTA. Thread (grp,col):
//   grp 0: bias + unified k in [0,144)   (x rows 0..31 + h rows 0..111)
//   grp 1:        unified k in [144,288) -> partials via SMEM
// grp 0 combines + state update; grp 1 stages x(t+1) and does the out-dot.

#define B_      1024
#define T_      365
#define DD      32
#define DS      27
#define H_      256
#define G3      768
#define M_      8
#define KTOT    288            // 32 x-k + 256 h-k (unified)
#define KG      144            // k per group
#define THREADS 512
#define CTAS    (B_ / M_)      // 128
#define PS_STRIDE 13           // padded partial stride (u64 per column)
#define HT_S    264

typedef unsigned long long u64;

// fp16 packed weights, unified k axis (k<32 -> W_ih row k, else W_hh row k-32)
// .x = {wf, wo} as half2 bits, .y = {wg, 0} as half2 bits
__device__ uint2 WP[KTOT][256];

__device__ __forceinline__ u64 pack2(float lo, float hi) {
    u64 r; asm("mov.b64 %0, {%1, %2};" : "=l"(r) : "f"(lo), "f"(hi)); return r;
}
__device__ __forceinline__ void unpack2(u64 v, float& lo, float& hi) {
    asm("mov.b64 {%0, %1}, %2;" : "=f"(lo), "=f"(hi) : "l"(v));
}
__device__ __forceinline__ void fma2(u64& d, u64 a, u64 b) {
    asm("fma.rn.f32x2 %0, %1, %2, %0;" : "+l"(d) : "l"(a), "l"(b));
}
__device__ __forceinline__ void add2(u64& d, u64 a) {
    asm("add.rn.f32x2 %0, %0, %1;" : "+l"(d) : "l"(a));
}
__device__ __forceinline__ float sigmoidf_(float x) {
    return __fdividef(1.0f, 1.0f + __expf(-x));
}
__device__ __forceinline__ float tanhf_(float x) {
    float e = __expf(-2.0f * x);
    return __fdividef(1.0f - e, 1.0f + e);
}

__global__ void __launch_bounds__(256)
repack_kernel(const float* __restrict__ Wih, const float* __restrict__ Whh) {
    const int k   = blockIdx.x;        // unified k: 0..287
    const int col = threadIdx.x;       // 0..255
    const float* s = (k < DD) ? (Wih + k * G3) : (Whh + (k - DD) * G3);
    __half2 w01 = __floats2half2_rn(s[col], s[256 + col]);      // (wf, wo)
    __half2 w2  = __floats2half2_rn(s[512 + col], 0.0f);        // (wg, 0)
    uint2 p;
    p.x = *reinterpret_cast<unsigned int*>(&w01);
    p.y = *reinterpret_cast<unsigned int*>(&w2);
    WP[k][col] = p;
}

__global__ void __launch_bounds__(THREADS, 1)
ealstm_kernel(const float* __restrict__ xd,      // [B, T, DD]
              const float* __restrict__ xs,      // [B, DS]
              const float* __restrict__ Wsh,     // [DS, H]
              const float* __restrict__ bias,    // [3H]
              const float* __restrict__ bias_s,  // [H]
              const float* __restrict__ Wout,    // [H, 1]
              const float* __restrict__ bout,    // [1]
              float* __restrict__ out)           // [B, T, 1]
{
    __shared__ __align__(16) float xh[KTOT * M_];  // k<32: x_t, else h (stride 8)
    __shared__ float h_t[M_][HT_S];                // h transposed for out-dot
    __shared__ u64   p_s[H_ * PS_STRIDE];          // group-1 partial gate sums

    const int j    = threadIdx.x;
    const int grp  = j >> 8;                // 0 or 1
    const int col  = j & 255;               // gate/h column
    const int b0   = blockIdx.x * M_;
    const int lane = j & 31;
    const int warp = j >> 5;
    const int k0   = grp * KG;              // unified k range start

    // zero h region of xh (indices [DD*M_, KTOT*M_))
    for (int idx = DD * M_ + j; idx < KTOT * M_; idx += THREADS) xh[idx] = 0.0f;

    // stage x_t for t = 0 (group 1's 256 threads)
    if (grp == 1) {
        const int m = col >> 5, k = col & 31;
        xh[k * M_ + m] = xd[((size_t)(b0 + m) * T_ + 0) * DD + k];
    }

    // per-thread gate biases (group 0 seeds accumulators)
    float bf = 0.0f, bo = 0.0f, bg = 0.0f;
    if (grp == 0) { bf = bias[col]; bo = bias[H_ + col]; bg = bias[2 * H_ + col]; }

    // entity-aware input gate (group 0 only)
    float ig[M_];
    if (grp == 0) {
        float s[M_];
        #pragma unroll
        for (int m = 0; m < M_; m++) s[m] = bias_s[col];
        #pragma unroll 1
        for (int k = 0; k < DS; k++) {
            const float w = Wsh[k * H_ + col];
            #pragma unroll
            for (int m = 0; m < M_; m++)
                s[m] = fmaf(xs[(b0 + m) * DS + k], w, s[m]);
        }
        #pragma unroll
        for (int m = 0; m < M_; m++) ig[m] = sigmoidf_(s[m]);
    }

    // per-lane output weights for the warp-level out-dot
    float wout[8];
    #pragma unroll
    for (int q = 0; q < 8; q++) wout[q] = Wout[lane + 32 * q];
    const float b_out0 = bout[0];

    float c[M_];
    #pragma unroll
    for (int m = 0; m < M_; m++) c[m] = 0.0f;

    __syncthreads();

    for (int t = 0; t < T_; t++) {
        u64 aF[4], aO[4], aG[4];
        if (grp == 0) {
            const u64 bf2 = pack2(bf, bf), bo2 = pack2(bo, bo), bg2 = pack2(bg, bg);
            #pragma unroll
            for (int p = 0; p < 4; p++) { aF[p] = bf2; aO[p] = bo2; aG[p] = bg2; }
        } else {
            #pragma unroll
            for (int p = 0; p < 4; p++) { aF[p] = 0ull; aO[p] = 0ull; aG[p] = 0ull; }
        }

        // ---- unified accumulation over this group's 144 k's ----
        {
            const uint2* wp = &WP[k0][col];
            const float* hb = xh + k0 * M_;
            #pragma unroll 4
            for (int k = 0; k < KG; k++) {
                const uint2 wbits = __ldcg(wp + k * 256);       // ONE LDG.64
                const __half2 w01 = *reinterpret_cast<const __half2*>(&wbits.x);
                const float2 f01  = __half22float2(w01);        // (wf, wo)
                const float  fg   = __half2float(
                    *reinterpret_cast<const __half*>(&wbits.y));
                const u64 wf2 = pack2(f01.x, f01.x);
                const u64 wo2 = pack2(f01.y, f01.y);
                const u64 wg2 = pack2(fg, fg);
                const ulonglong2 hA = *(const ulonglong2*)(hb + k * M_);
                const ulonglong2 hB = *(const ulonglong2*)(hb + k * M_ + 4);
                fma2(aF[0], wf2, hA.x); fma2(aF[1], wf2, hA.y);
                fma2(aF[2], wf2, hB.x); fma2(aF[3], wf2, hB.y);
                fma2(aO[0], wo2, hA.x); fma2(aO[1], wo2, hA.y);
                fma2(aO[2], wo2, hB.x); fma2(aO[3], wo2, hB.y);
                fma2(aG[0], wg2, hA.x); fma2(aG[1], wg2, hA.y);
                fma2(aG[2], wg2, hB.x); fma2(aG[3], wg2, hB.y);
            }
        }

        // group 1 publishes partials (per-col contiguous layout)
        if (grp == 1) {
            u64* pp = p_s + col * PS_STRIDE;
            #pragma unroll
            for (int p = 0; p < 4; p++) {
                pp[p]     = aF[p];
                pp[4 + p] = aO[p];
                pp[8 + p] = aG[p];
            }
        }

        __syncthreads();   // partials published; xh reads of step t done

        if (grp == 0) {
            // combine partials + state update
            const u64* pp = p_s + col * PS_STRIDE;
            #pragma unroll
            for (int p = 0; p < 4; p++) {
                add2(aF[p], pp[p]);
                add2(aO[p], pp[4 + p]);
                add2(aG[p], pp[8 + p]);
            }
            float hn[M_];
            #pragma unroll
            for (int p = 0; p < 4; p++) {
                float f0, f1, o0, o1, g0, g1;
                unpack2(aF[p], f0, f1);
                unpack2(aO[p], o0, o1);
                unpack2(aG[p], g0, g1);
                const int m0 = 2 * p, m1 = 2 * p + 1;
                c[m0] = sigmoidf_(f0) * c[m0] + ig[m0] * tanhf_(g0);
                c[m1] = sigmoidf_(f1) * c[m1] + ig[m1] * tanhf_(g1);
                hn[m0] = sigmoidf_(o0) * tanhf_(c[m0]);
                hn[m1] = sigmoidf_(o1) * tanhf_(c[m1]);
            }
            // publish h into xh h-region (stride-8 aligned, vectorized)
            float* hd = xh + (DD + col) * M_;
            *(float4*)(hd)     = make_float4(hn[0], hn[1], hn[2], hn[3]);
            *(float4*)(hd + 4) = make_float4(hn[4], hn[5], hn[6], hn[7]);
            // transposed copy for the out-dot
            #pragma unroll
            for (int m = 0; m < M_; m++) h_t[m][col] = hn[m];
        } else {
            // stage x for t+1 (x region: disjoint from h region)
            if (t + 1 < T_) {
                const int m = col >> 5, k = col & 31;
                xh[k * M_ + m] = xd[((size_t)(b0 + m) * T_ + (t + 1)) * DD + k];
            }
        }

        __syncthreads();   // h(t), h_t(t), x(t+1) published

        // output dot: group-1 warps (8..15) own batch elems 0..7
        if (grp == 1) {
            const int w = warp - 8;   // 0..7 = batch element m
            float a = 0.0f;
            #pragma unroll
            for (int q = 0; q < 8; q++)
                a = fmaf(h_t[w][lane + 32 * q], wout[q], a);
            #pragma unroll
            for (int off = 16; off > 0; off >>= 1)
                a += __shfl_down_sync(0xffffffffu, a, off);
            if (lane == 0)
                out[(size_t)(b0 + w) * T_ + t] = a + b_out0;
        }
        // h_t isn't rewritten until after the next step's first sync, so this
        // post-sync read overlap is race-free.
    }
}

extern "C" void kernel_launch(void* const* d_in, const int* in_sizes, int n_in,
                              void* d_out, int out_size) {
    const float* xd     = (const float*)d_in[0];  // x_dynamic [1024,365,32]
    const float* xs     = (const float*)d_in[1];  // x_static  [1024,27]
    const float* Wih    = (const float*)d_in[2];  // [32,768]
    const float* Whh    = (const float*)d_in[3];  // [256,768]
    const float* Wsh    = (const float*)d_in[4];  // [27,256]
    const float* bias   = (const float*)d_in[5];  // [768]
    const float* bias_s = (const float*)d_in[6];  // [256]
    const float* Wout   = (const float*)d_in[7];  // [256,1]
    const float* bout   = (const float*)d_in[8];  // [1]
    float* out = (float*)d_out;                   // [1024,365,1]

    repack_kernel<<<KTOT, 256>>>(Wih, Whh);
    ealstm_kernel<<<CTAS, THREADS>>>(xd, xs, Wsh, bias, bias_s,
                                     Wout, bout, out);
}